// round 14
// baseline (speedup 1.0000x reference)
#include <cuda_runtime.h>
#include <cuda_fp16.h>
#include <math.h>

constexpr int NL    = 4;
constexpr int DIM   = 512;
constexpr int NH    = 8;
constexpr int HD    = 64;
constexpr int DFFN  = 2048;
constexpr int SEQ   = 512;
constexpr int BATCH = 16;
constexpr int NCLS  = 3;
constexpr int MR    = BATCH * SEQ;  // 8192
constexpr int NBH   = BATCH * NH;   // 128

// ---------------- scratch ----------------
__device__ float  g_x  [MR * DIM];                 // residual stream (fp32)
__device__ float  g_hf [MR * DIM];                 // final LN output (fp32)
__device__ __half g_h  [MR * DIM];                 // LN output (fp16)
__device__ __half g_q  [MR * DIM];                 // [B,H,N,HD] (pre-scaled by 1/8)
__device__ __half g_k  [MR * DIM];                 // [B,H,N,HD]
__device__ __half g_v  [MR * DIM];                 // [B,H,N,HD]
__device__ __half g_ctx[MR * DIM];
__device__ __half g_ffn[MR * DFFN];
__device__ __half g_wh [12582912];                 // all weights fp16
__device__ float  g_la [MR * NCLS];
__device__ float  g_lb [MR * NCLS];

constexpr size_t OWQ = 0;
constexpr size_t OWK = OWQ + (size_t)NL * DIM * DIM;
constexpr size_t OWV = OWK + (size_t)NL * DIM * DIM;
constexpr size_t OWO = OWV + (size_t)NL * DIM * DIM;
constexpr size_t OW1 = OWO + (size_t)NL * DIM * DIM;
constexpr size_t OW2 = OW1 + (size_t)NL * DIM * DFFN;

struct QKVArgs {
    const __half* w[3];
    const float*  b[3];
    __half*       o[3];
};

// ---------------- fp32 -> fp16 weight conversion ----------------
__global__ void f2h4_kernel(const float* __restrict__ src, __half* __restrict__ dst, int n4) {
    int i = blockIdx.x * blockDim.x + threadIdx.x;
    if (i >= n4) return;
    float4 f = ((const float4*)src)[i];
    ((__half2*)dst)[2 * i]     = __floats2half2_rn(f.x, f.y);
    ((__half2*)dst)[2 * i + 1] = __floats2half2_rn(f.z, f.w);
}

// ---------------- embedding + PE ----------------
__global__ void embed_kernel(const int* __restrict__ src,
                             const float* __restrict__ emb) {
    int idx = blockIdx.x * blockDim.x + threadIdx.x;
    if (idx >= MR * DIM) return;
    int d = idx % DIM;
    int m = idx / DIM;
    int b = m / SEQ;
    int n = m % SEQ;
    int tok = src[n * BATCH + b];
    float e = emb[(size_t)tok * DIM + d] * 22.62741699796952f;
    int i2 = (d >> 1) * 2;
    float freq = expf((float)i2 * (-9.210340371976184f / (float)DIM));
    float ang = (float)n * freq;
    float pe = (d & 1) ? cosf(ang) : sinf(ang);
    g_x[idx] = e + pe;
}

// ---------------- LayerNorm (OH: 1 = half out, 0 = float out) -------------
template<int OH>
__global__ void ln_kernel(const float* __restrict__ in, void* __restrict__ out,
                          const float* __restrict__ gg, const float* __restrict__ bb) {
    int row = blockIdx.x;
    int t = threadIdx.x;
    const float* p = in + (size_t)row * DIM;
    float v[4];
    float s = 0.f, ss = 0.f;
#pragma unroll
    for (int i = 0; i < 4; i++) {
        float x = p[t + i * 128];
        v[i] = x; s += x; ss += x * x;
    }
#pragma unroll
    for (int off = 16; off >= 1; off >>= 1) {
        s  += __shfl_xor_sync(0xffffffffu, s, off);
        ss += __shfl_xor_sync(0xffffffffu, ss, off);
    }
    __shared__ float rs[4], rss[4];
    int w = t >> 5, lane = t & 31;
    if (lane == 0) { rs[w] = s; rss[w] = ss; }
    __syncthreads();
    float S  = rs[0] + rs[1] + rs[2] + rs[3];
    float SS = rss[0] + rss[1] + rss[2] + rss[3];
    float mean = S * (1.f / DIM);
    float var  = SS * (1.f / DIM) - mean * mean;
    float rstd = rsqrtf(var + 1e-6f);
#pragma unroll
    for (int i = 0; i < 4; i++) {
        int c = t + i * 128;
        float o = (v[i] - mean) * rstd * gg[c] + bb[c];
        if (OH) ((__half*)out)[(size_t)row * DIM + c] = __float2half(o);
        else    ((float*)out)[(size_t)row * DIM + c]  = o;
    }
}

// ---------------- fp16 mma helpers ----------------
__device__ __forceinline__ unsigned s2u(const void* p) {
    return (unsigned)__cvta_generic_to_shared(p);
}

__device__ __forceinline__ void cp16(void* smem, const void* gmem) {
    asm volatile("cp.async.cg.shared.global [%0], [%1], 16;"
                 :: "r"(s2u(smem)), "l"(gmem));
}

__device__ __forceinline__ void mma_f16(float c[4], const unsigned a[4], const unsigned b[2]) {
    asm volatile(
        "mma.sync.aligned.m16n8k16.row.col.f32.f16.f16.f32 "
        "{%0,%1,%2,%3}, {%4,%5,%6,%7}, {%8,%9}, {%0,%1,%2,%3};"
        : "+f"(c[0]), "+f"(c[1]), "+f"(c[2]), "+f"(c[3])
        : "r"(a[0]), "r"(a[1]), "r"(a[2]), "r"(a[3]),
          "r"(b[0]), "r"(b[1]));
}

// ---------------- fp16 tensor-core GEMM (BK=64, 3-stage cp.async) ---------
// BM=128, BN=128, 256 threads (8 warps, warp tile 64x32). 8 syncs per K=512.
// EPI: 0 bias, 1 bias+residual(f32), 2 bias+relu
// SCAT: 0 plain, 4 fused-QKV (z selects W/bias/out; z==0 scales by 1/8)
// CH: output stored as half (1) or float (0)
constexpr int TG_BK   = 64;
constexpr int TG_LDA  = 72;   // A row pitch (halves), odd*16B -> conflict-free
constexpr int TG_LDB  = 136;  // B row pitch (halves)
constexpr int TG_STG  = 3;
constexpr int TG_SMEM = TG_STG * (128 * TG_LDA + TG_BK * TG_LDB) * 2;  // 107520 B

template<int EPI, int SCAT, int CH>
__global__ __launch_bounds__(256, 2)
void tgemm(const __half* __restrict__ A, const __half* __restrict__ W,
           const float* __restrict__ bias, const float* __restrict__ resid,
           void* __restrict__ Cv, int K, int lda, int ldb, int ldc,
           long long sA, long long sB, long long sC, QKVArgs qa) {
    constexpr int BK  = TG_BK;
    constexpr int LDA = TG_LDA;
    constexpr int LDB = TG_LDB;

    extern __shared__ char smbuf[];
    __half (*As)[128][LDA] = (__half(*)[128][LDA])smbuf;
    __half (*Bs)[BK][LDB]  = (__half(*)[BK][LDB])(smbuf + TG_STG * 128 * LDA * 2);

    const int tid  = threadIdx.x;
    const int w    = tid >> 5;
    const int lane = tid & 31;
    const int g    = lane >> 2;
    const int tq   = lane & 3;
    const int lane15 = lane & 15;
    const int aoff = (lane >> 4) << 3;
    const int wrow = (w & 1) * 64;
    const int wcol = (w >> 1) * 32;
    const int z    = blockIdx.z;
    const int row0 = blockIdx.y * 128;
    const int col0 = blockIdx.x * 128;

    const float* bias_p = bias;
    __half* Co_h = (__half*)Cv;
    float*  Co_f = (float*)Cv;
    if (SCAT == 4) {
        W      = qa.w[z];
        bias_p = qa.b[z];
        Co_h   = qa.o[z];
    } else {
        A += (size_t)z * sA;
        W += (size_t)z * sB;
    }

    // loaders: A 128x64 halves (2 threads/row, 4 cp16 each);
    //          B 64x128 halves (16 rows x 16 cols of cp16, 4 rows/thread)
    const int arow = tid >> 1;
    const int acol = (tid & 1) * 32;
    const int brow = tid >> 4;
    const int bcol = (tid & 15) * 8;

    const __half* Ap = A + (size_t)(row0 + arow) * lda + acol;
    const __half* Wp = W + (size_t)brow * ldb + col0 + bcol;

    float C[4][4][4];
#pragma unroll
    for (int i = 0; i < 4; i++)
#pragma unroll
        for (int j = 0; j < 4; j++)
#pragma unroll
            for (int q = 0; q < 4; q++) C[i][j][q] = 0.f;

    const int nblk = K / BK;  // >= 8 for all uses

    auto issue = [&](int buf, int blk) {
        const __half* ap = Ap + blk * BK;
#pragma unroll
        for (int i = 0; i < 4; i++)
            cp16(&As[buf][arow][acol + i * 8], ap + i * 8);
#pragma unroll
        for (int rr = 0; rr < 4; rr++)
            cp16(&Bs[buf][brow + rr * 16][bcol], Wp + (size_t)(blk * BK + rr * 16) * ldb);
        asm volatile("cp.async.commit_group;");
    };

    issue(0, 0);
    issue(1, 1);
    asm volatile("cp.async.wait_group 1;");
    __syncthreads();

    int s = 0;
    for (int blk = 0; blk < nblk; blk++) {
        if (blk + 2 < nblk) issue((blk + 2) % TG_STG, blk + 2);

#pragma unroll
        for (int ks = 0; ks < 4; ks++) {
            const int kb = ks * 16;
            unsigned af[4][4], bf[4][2];
#pragma unroll
            for (int mt = 0; mt < 4; mt++) {
                unsigned addr = s2u(&As[s][wrow + mt * 16 + lane15][kb + aoff]);
                asm volatile("ldmatrix.sync.aligned.m8n8.x4.shared.b16 {%0,%1,%2,%3}, [%4];"
                             : "=r"(af[mt][0]), "=r"(af[mt][1]), "=r"(af[mt][2]), "=r"(af[mt][3])
                             : "r"(addr));
            }
#pragma unroll
            for (int nt = 0; nt < 4; nt++) {
                unsigned addr = s2u(&Bs[s][kb + lane15][wcol + nt * 8]);
                asm volatile("ldmatrix.sync.aligned.m8n8.x2.trans.shared.b16 {%0,%1}, [%2];"
                             : "=r"(bf[nt][0]), "=r"(bf[nt][1])
                             : "r"(addr));
            }
#pragma unroll
            for (int mt = 0; mt < 4; mt++)
#pragma unroll
                for (int nt = 0; nt < 4; nt++)
                    mma_f16(C[mt][nt], af[mt], bf[nt]);
        }

        if (blk + 2 < nblk) {
            asm volatile("cp.async.wait_group 1;");
            __syncthreads();
        } else if (blk + 1 < nblk) {
            asm volatile("cp.async.wait_group 0;");
            __syncthreads();
        }
        s = (s + 1) % TG_STG;
    }

#pragma unroll
    for (int mt = 0; mt < 4; mt++) {
#pragma unroll
        for (int half = 0; half < 2; half++) {
            int r = row0 + wrow + mt * 16 + g + half * 8;
#pragma unroll
            for (int nt = 0; nt < 4; nt++) {
                int c = col0 + wcol + nt * 8 + tq * 2;
                float v0 = C[mt][nt][half * 2 + 0] + bias_p[c];
                float v1 = C[mt][nt][half * 2 + 1] + bias_p[c + 1];
                if (EPI == 1) {
                    const float* rp = resid + (size_t)r * ldc + c;
                    v0 += rp[0]; v1 += rp[1];
                }
                if (EPI == 2) { v0 = fmaxf(v0, 0.f); v1 = fmaxf(v1, 0.f); }
                if (SCAT == 4) {
                    if (z == 0) { v0 *= 0.125f; v1 *= 0.125f; }
                    int b = r >> 9, n = r & 511, hh = c >> 6, dd = c & 63;
                    *(__half2*)(Co_h + (((size_t)(b * NH + hh)) * SEQ + n) * HD + dd) =
                        __floats2half2_rn(v0, v1);
                } else {
                    if (CH)
                        *(__half2*)(Co_h + (size_t)z * sC + (size_t)r * ldc + c) =
                            __floats2half2_rn(v0, v1);
                    else
                        *(float2*)(Co_f + (size_t)z * sC + (size_t)r * ldc + c) =
                            make_float2(v0, v1);
                }
            }
        }
    }
}

// ---------------- fused flash attention ----------------
constexpr int LDQ = 72;
constexpr int ATTN_SMEM = (128 * LDQ + 2 * 64 * LDQ + 2 * 64 * LDQ) * 2;  // 55296 B

__global__ __launch_bounds__(256, 1)
void attn_kernel(const int* __restrict__ lengths) {
    extern __shared__ __half sm[];
    __half (*Q_sm)[LDQ] = (__half(*)[LDQ])sm;
    __half (*K_sm)[LDQ] = (__half(*)[LDQ])(sm + 128 * LDQ);
    __half (*V_sm)[LDQ] = (__half(*)[LDQ])(sm + 256 * LDQ);

    const int tid  = threadIdx.x;
    const int w    = tid >> 5;
    const int lane = tid & 31;
    const int g    = lane >> 2;
    const int tq   = lane & 3;
    const int lane15 = lane & 15;
    const int aoff = (lane >> 4) << 3;
    const int bh = blockIdx.y;
    const int b  = bh >> 3;
    const int hh = bh & 7;
    const int q0 = blockIdx.x * 128;
    const int qbase = w * 16;
    const int len = lengths[b];

    const __half* Qg = g_q + ((size_t)bh * SEQ + q0) * HD;
    const __half* Kg = g_k + (size_t)bh * SEQ * HD;
    const __half* Vg = g_v + (size_t)bh * SEQ * HD;

    {
        int r = tid >> 1, cb = (tid & 1) * 32;
        const __half* qp = Qg + (size_t)r * HD + cb;
#pragma unroll
        for (int i = 0; i < 4; i++)
            *(uint4*)&Q_sm[r][cb + i * 8] = *(const uint4*)(qp + i * 8);
    }
    const int kr = tid >> 2, kc = (tid & 3) * 16;
    uint4 ka, kb2, va, vb;
    ka  = *(const uint4*)(Kg + (size_t)kr * HD + kc);
    kb2 = *(const uint4*)(Kg + (size_t)kr * HD + kc + 8);
    va  = *(const uint4*)(Vg + (size_t)kr * HD + kc);
    vb  = *(const uint4*)(Vg + (size_t)kr * HD + kc + 8);
    *(uint4*)&K_sm[kr][kc]     = ka;
    *(uint4*)&K_sm[kr][kc + 8] = kb2;
    *(uint4*)&V_sm[kr][kc]     = va;
    *(uint4*)&V_sm[kr][kc + 8] = vb;
    __syncthreads();

    unsigned qf[4][4];
#pragma unroll
    for (int k = 0; k < 4; k++) {
        unsigned addr = s2u(&Q_sm[qbase + lane15][k * 16 + aoff]);
        asm volatile("ldmatrix.sync.aligned.m8n8.x4.shared.b16 {%0,%1,%2,%3}, [%4];"
                     : "=r"(qf[k][0]), "=r"(qf[k][1]), "=r"(qf[k][2]), "=r"(qf[k][3])
                     : "r"(addr));
    }

    float ctx[8][4];
#pragma unroll
    for (int i = 0; i < 8; i++)
#pragma unroll
        for (int j = 0; j < 4; j++) ctx[i][j] = 0.f;
    float rs0 = 0.f, rs1 = 0.f;

    int s = 0;
    for (int c = 0; c < 8; c++) {
        if (c + 1 < 8) {
            const __half* kp = Kg + (size_t)((c + 1) * 64 + kr) * HD + kc;
            const __half* vp = Vg + (size_t)((c + 1) * 64 + kr) * HD + kc;
            ka  = *(const uint4*)(kp);
            kb2 = *(const uint4*)(kp + 8);
            va  = *(const uint4*)(vp);
            vb  = *(const uint4*)(vp + 8);
        }

        float S[8][4];
#pragma unroll
        for (int i = 0; i < 8; i++)
#pragma unroll
            for (int j = 0; j < 4; j++) S[i][j] = 0.f;
#pragma unroll
        for (int k = 0; k < 4; k++) {
            unsigned bk[4][4];
#pragma unroll
            for (int p = 0; p < 4; p++) {
                unsigned addr = s2u(&K_sm[s * 64 + p * 16 + lane15][k * 16 + aoff]);
                asm volatile("ldmatrix.sync.aligned.m8n8.x4.shared.b16 {%0,%1,%2,%3}, [%4];"
                             : "=r"(bk[p][0]), "=r"(bk[p][1]), "=r"(bk[p][2]), "=r"(bk[p][3])
                             : "r"(addr));
            }
#pragma unroll
            for (int p = 0; p < 4; p++) {
                unsigned bfa[2] = {bk[p][0], bk[p][2]};
                unsigned bfb[2] = {bk[p][1], bk[p][3]};
                mma_f16(S[2 * p],     qf[k], bfa);
                mma_f16(S[2 * p + 1], qf[k], bfb);
            }
        }

        unsigned pl[8], ph[8];
        const int kbase = c * 64 + tq * 2;
#pragma unroll
        for (int nt = 0; nt < 8; nt++) {
            int key = kbase + nt * 8;
            bool m0 = key < len, m1 = key + 1 < len;
            float e0 = m0 ? __expf(S[nt][0]) : 0.f;
            float e1 = m1 ? __expf(S[nt][1]) : 0.f;
            float e2 = m0 ? __expf(S[nt][2]) : 0.f;
            float e3 = m1 ? __expf(S[nt][3]) : 0.f;
            __half2 h0 = __floats2half2_rn(e0, e1);
            __half2 h1 = __floats2half2_rn(e2, e3);
            pl[nt] = *(unsigned*)&h0;
            ph[nt] = *(unsigned*)&h1;
            float2 f0 = __half22float2(h0);
            float2 f1 = __half22float2(h1);
            rs0 += f0.x + f0.y;
            rs1 += f1.x + f1.y;
        }

#pragma unroll
        for (int j = 0; j < 4; j++) {
            unsigned af[4] = {pl[2 * j], ph[2 * j], pl[2 * j + 1], ph[2 * j + 1]};
#pragma unroll
            for (int nt = 0; nt < 8; nt++) {
                unsigned bf[2];
                unsigned addr = s2u(&V_sm[s * 64 + j * 16 + lane15][nt * 8]);
                asm volatile("ldmatrix.sync.aligned.m8n8.x2.trans.shared.b16 {%0,%1}, [%2];"
                             : "=r"(bf[0]), "=r"(bf[1])
                             : "r"(addr));
                mma_f16(ctx[nt], af, bf);
            }
        }

        if (c + 1 < 8) {
            int ns = s ^ 1;
            *(uint4*)&K_sm[ns * 64 + kr][kc]     = ka;
            *(uint4*)&K_sm[ns * 64 + kr][kc + 8] = kb2;
            *(uint4*)&V_sm[ns * 64 + kr][kc]     = va;
            *(uint4*)&V_sm[ns * 64 + kr][kc + 8] = vb;
            __syncthreads();
            s = ns;
        }
    }

    rs0 += __shfl_xor_sync(0xffffffffu, rs0, 1);
    rs0 += __shfl_xor_sync(0xffffffffu, rs0, 2);
    rs1 += __shfl_xor_sync(0xffffffffu, rs1, 1);
    rs1 += __shfl_xor_sync(0xffffffffu, rs1, 2);
    float i0 = 1.f / rs0;
    float i1 = 1.f / rs1;

    int q = q0 + qbase + g;
#pragma unroll
    for (int nt = 0; nt < 8; nt++) {
        int col = hh * HD + nt * 8 + tq * 2;
        *(__half2*)(g_ctx + (size_t)(b * SEQ + q) * DIM + col) =
            __floats2half2_rn(ctx[nt][0] * i0, ctx[nt][1] * i0);
        *(__half2*)(g_ctx + (size_t)(b * SEQ + q + 8) * DIM + col) =
            __floats2half2_rn(ctx[nt][2] * i1, ctx[nt][3] * i1);
    }
}

// ---------------- outputs ----------------
__global__ void out1_kernel(float* __restrict__ out1) {
    int idx = blockIdx.x * blockDim.x + threadIdx.x;
    if (idx >= MR * DIM) return;
    int d = idx % DIM;
    int nb = idx / DIM;
    int b = nb % BATCH;
    int n = nb / BATCH;
    out1[idx] = g_hf[((size_t)b * SEQ + n) * DIM + d];
}

__global__ void infw_kernel(const float* __restrict__ W) {
    int mrow = blockIdx.x;
    int t = threadIdx.x;  // 64
    float a[NCLS] = {0, 0, 0}, bv2[NCLS] = {0, 0, 0};
    const float* xp = g_hf + (size_t)mrow * DIM;
    for (int d = t; d < DIM; d += 64) {
        float xv = xp[d];
#pragma unroll
        for (int c = 0; c < NCLS; c++) {
            a[c]   += xv * W[(size_t)d * NCLS + c];
            bv2[c] += xv * W[(size_t)(DIM + d) * NCLS + c];
        }
    }
    __shared__ float red[6][64];
#pragma unroll
    for (int c = 0; c < NCLS; c++) { red[c][t] = a[c]; red[3 + c][t] = bv2[c]; }
    __syncthreads();
    for (int sft = 32; sft >= 1; sft >>= 1) {
        if (t < sft) {
#pragma unroll
            for (int c = 0; c < 6; c++) red[c][t] += red[c][t + sft];
        }
        __syncthreads();
    }
    if (t == 0) {
#pragma unroll
        for (int c = 0; c < NCLS; c++) {
            g_la[mrow * NCLS + c] = red[c][0];
            g_lb[mrow * NCLS + c] = red[3 + c][0];
        }
    }
}

__global__ void pair_kernel(float* __restrict__ out2) {
    int idx = blockIdx.x * blockDim.x + threadIdx.x;
    if (idx >= SEQ * SEQ * BATCH) return;
    int b = idx % BATCH;
    int j = (idx / BATCH) % SEQ;
    int i = idx / (BATCH * SEQ);
    const float* lap = g_la + ((size_t)b * SEQ + i) * NCLS;
    const float* lbp = g_lb + ((size_t)b * SEQ + j) * NCLS;
    float v0 = lap[0] + lbp[0];
    float v1 = lap[1] + lbp[1];
    float v2 = lap[2] + lbp[2];
    float mx = fmaxf(v0, fmaxf(v1, v2));
    float lse = mx + logf(expf(v0 - mx) + expf(v1 - mx) + expf(v2 - mx));
    float* o = out2 + (size_t)idx * NCLS;
    o[0] = v0 - lse; o[1] = v1 - lse; o[2] = v2 - lse;
}

// ---------------- orchestration ----------------
extern "C" void kernel_launch(void* const* d_in, const int* in_sizes, int n_in,
                              void* d_out, int out_size) {
    (void)in_sizes; (void)n_in; (void)out_size;
    const int*   src     = (const int*)  d_in[0];
    const int*   lengths = (const int*)  d_in[1];
    const float* emb     = (const float*)d_in[2];
    const float* ln1_g   = (const float*)d_in[3];
    const float* ln1_b   = (const float*)d_in[4];
    const float* Wq      = (const float*)d_in[5];
    const float* bq      = (const float*)d_in[6];
    const float* Wk      = (const float*)d_in[7];
    const float* bk      = (const float*)d_in[8];
    const float* Wv      = (const float*)d_in[9];
    const float* bv      = (const float*)d_in[10];
    const float* Wo      = (const float*)d_in[11];
    const float* bo      = (const float*)d_in[12];
    const float* ln2_g   = (const float*)d_in[13];
    const float* ln2_b   = (const float*)d_in[14];
    const float* W1      = (const float*)d_in[15];
    const float* b1      = (const float*)d_in[16];
    const float* W2      = (const float*)d_in[17];
    const float* b2      = (const float*)d_in[18];
    const float* lnf_g   = (const float*)d_in[19];
    const float* lnf_b   = (const float*)d_in[20];
    const float* inf_W   = (const float*)d_in[21];
    float* out = (float*)d_out;

    float *px, *phf;
    __half *ph, *pq, *pk, *pv, *pctx, *pffn, *pwh;
    cudaGetSymbolAddress((void**)&px,   g_x);
    cudaGetSymbolAddress((void**)&phf,  g_hf);
    cudaGetSymbolAddress((void**)&ph,   g_h);
    cudaGetSymbolAddress((void**)&pq,   g_q);
    cudaGetSymbolAddress((void**)&pk,   g_k);
    cudaGetSymbolAddress((void**)&pv,   g_v);
    cudaGetSymbolAddress((void**)&pctx, g_ctx);
    cudaGetSymbolAddress((void**)&pffn, g_ffn);
    cudaGetSymbolAddress((void**)&pwh,  g_wh);

    cudaFuncSetAttribute(attn_kernel, cudaFuncAttributeMaxDynamicSharedMemorySize,
                         ATTN_SMEM);
    cudaFuncSetAttribute(tgemm<0, 4, 1>, cudaFuncAttributeMaxDynamicSharedMemorySize,
                         TG_SMEM);
    cudaFuncSetAttribute(tgemm<1, 0, 0>, cudaFuncAttributeMaxDynamicSharedMemorySize,
                         TG_SMEM);
    cudaFuncSetAttribute(tgemm<2, 0, 1>, cudaFuncAttributeMaxDynamicSharedMemorySize,
                         TG_SMEM);

    // one-time weight fp32->fp16 conversion
    const int nQ = NL * DIM * DIM;
    const int nF = NL * DIM * DFFN;
    f2h4_kernel<<<(nQ / 4 + 255) / 256, 256>>>(Wq, pwh + OWQ, nQ / 4);
    f2h4_kernel<<<(nQ / 4 + 255) / 256, 256>>>(Wk, pwh + OWK, nQ / 4);
    f2h4_kernel<<<(nQ / 4 + 255) / 256, 256>>>(Wv, pwh + OWV, nQ / 4);
    f2h4_kernel<<<(nQ / 4 + 255) / 256, 256>>>(Wo, pwh + OWO, nQ / 4);
    f2h4_kernel<<<(nF / 4 + 255) / 256, 256>>>(W1, pwh + OW1, nF / 4);
    f2h4_kernel<<<(nF / 4 + 255) / 256, 256>>>(W2, pwh + OW2, nF / 4);

    embed_kernel<<<(MR * DIM + 255) / 256, 256>>>(src, emb);

    QKVArgs qe = {};

    for (int l = 0; l < NL; l++) {
        const __half* wq = pwh + OWQ + (size_t)l * DIM * DIM;
        const __half* wk = pwh + OWK + (size_t)l * DIM * DIM;
        const __half* wv = pwh + OWV + (size_t)l * DIM * DIM;
        const __half* wo = pwh + OWO + (size_t)l * DIM * DIM;
        const __half* w1 = pwh + OW1 + (size_t)l * DIM * DFFN;
        const __half* w2 = pwh + OW2 + (size_t)l * DFFN * DIM;

        ln_kernel<1><<<MR, 128>>>(px, ph, ln1_g + l * DIM, ln1_b + l * DIM);

        QKVArgs qa;
        qa.w[0] = wq; qa.w[1] = wk; qa.w[2] = wv;
        qa.b[0] = bq + l * DIM; qa.b[1] = bk + l * DIM; qa.b[2] = bv + l * DIM;
        qa.o[0] = pq; qa.o[1] = pk; qa.o[2] = pv;
        dim3 gQKV(DIM / 128, MR / 128, 3);
        tgemm<0, 4, 1><<<gQKV, 256, TG_SMEM>>>(ph, nullptr, nullptr, nullptr, nullptr,
                                               DIM, DIM, DIM, DIM, 0, 0, 0, qa);

        dim3 gA(SEQ / 128, NBH);
        attn_kernel<<<gA, 256, ATTN_SMEM>>>(lengths);

        dim3 gD(DIM / 128, MR / 128, 1);
        tgemm<1, 0, 0><<<gD, 256, TG_SMEM>>>(pctx, wo, bo + l * DIM, px, px,
                                             DIM, DIM, DIM, DIM, 0, 0, 0, qe);

        ln_kernel<1><<<MR, 128>>>(px, ph, ln2_g + l * DIM, ln2_b + l * DIM);

        dim3 gF(DFFN / 128, MR / 128, 1);
        tgemm<2, 0, 1><<<gF, 256, TG_SMEM>>>(ph, w1, b1 + l * DFFN, nullptr, pffn,
                                             DIM, DIM, DFFN, DFFN, 0, 0, 0, qe);
        tgemm<1, 0, 0><<<gD, 256, TG_SMEM>>>(pffn, w2, b2 + l * DIM, px, px,
                                             DFFN, DFFN, DIM, DIM, 0, 0, 0, qe);
    }

    ln_kernel<0><<<MR, 128>>>(px, phf, lnf_g, lnf_b);

    out1_kernel<<<(MR * DIM + 255) / 256, 256>>>(out);
    infw_kernel<<<MR, 64>>>(inf_W);
    pair_kernel<<<(SEQ * SEQ * BATCH + 255) / 256, 256>>>(out + (size_t)MR * DIM);
}

// round 15
// speedup vs baseline: 1.0246x; 1.0246x over previous
#include <cuda_runtime.h>
#include <cuda_fp16.h>
#include <math.h>

constexpr int NL    = 4;
constexpr int DIM   = 512;
constexpr int NH    = 8;
constexpr int HD    = 64;
constexpr int DFFN  = 2048;
constexpr int SEQ   = 512;
constexpr int BATCH = 16;
constexpr int NCLS  = 3;
constexpr int MR    = BATCH * SEQ;  // 8192
constexpr int NBH   = BATCH * NH;   // 128

// ---------------- scratch ----------------
__device__ float  g_x  [MR * DIM];                 // residual stream (fp32)
__device__ float  g_hf [MR * DIM];                 // final LN output (fp32)
__device__ __half g_h  [MR * DIM];                 // LN output (fp16)
__device__ __half g_q  [MR * DIM];                 // [B,H,N,HD] (pre-scaled by 1/8)
__device__ __half g_k  [MR * DIM];                 // [B,H,N,HD]
__device__ __half g_v  [MR * DIM];                 // [B,H,N,HD]
__device__ __half g_ctx[MR * DIM];
__device__ __half g_ffn[MR * DFFN];
__device__ __half g_wh [12582912];                 // all weights fp16
__device__ float  g_la [MR * NCLS];
__device__ float  g_lb [MR * NCLS];

constexpr size_t OWQ = 0;
constexpr size_t OWK = OWQ + (size_t)NL * DIM * DIM;
constexpr size_t OWV = OWK + (size_t)NL * DIM * DIM;
constexpr size_t OWO = OWV + (size_t)NL * DIM * DIM;
constexpr size_t OW1 = OWO + (size_t)NL * DIM * DIM;
constexpr size_t OW2 = OW1 + (size_t)NL * DIM * DFFN;

struct QKVArgs {
    const __half* w[3];
    const float*  b[3];
    __half*       o[3];
};

// ---------------- fp32 -> fp16 weight conversion ----------------
__global__ void f2h4_kernel(const float* __restrict__ src, __half* __restrict__ dst, int n4) {
    int i = blockIdx.x * blockDim.x + threadIdx.x;
    if (i >= n4) return;
    float4 f = ((const float4*)src)[i];
    ((__half2*)dst)[2 * i]     = __floats2half2_rn(f.x, f.y);
    ((__half2*)dst)[2 * i + 1] = __floats2half2_rn(f.z, f.w);
}

// ---------------- embedding + PE ----------------
__global__ void embed_kernel(const int* __restrict__ src,
                             const float* __restrict__ emb) {
    int idx = blockIdx.x * blockDim.x + threadIdx.x;
    if (idx >= MR * DIM) return;
    int d = idx % DIM;
    int m = idx / DIM;
    int b = m / SEQ;
    int n = m % SEQ;
    int tok = src[n * BATCH + b];
    float e = emb[(size_t)tok * DIM + d] * 22.62741699796952f;
    int i2 = (d >> 1) * 2;
    float freq = expf((float)i2 * (-9.210340371976184f / (float)DIM));
    float ang = (float)n * freq;
    float pe = (d & 1) ? cosf(ang) : sinf(ang);
    g_x[idx] = e + pe;
}

// ---------------- LayerNorm (OH: 1 = half out, 0 = float out) -------------
template<int OH>
__global__ void ln_kernel(const float* __restrict__ in, void* __restrict__ out,
                          const float* __restrict__ gg, const float* __restrict__ bb) {
    int row = blockIdx.x;
    int t = threadIdx.x;
    const float* p = in + (size_t)row * DIM;
    float v[4];
    float s = 0.f, ss = 0.f;
#pragma unroll
    for (int i = 0; i < 4; i++) {
        float x = p[t + i * 128];
        v[i] = x; s += x; ss += x * x;
    }
#pragma unroll
    for (int off = 16; off >= 1; off >>= 1) {
        s  += __shfl_xor_sync(0xffffffffu, s, off);
        ss += __shfl_xor_sync(0xffffffffu, ss, off);
    }
    __shared__ float rs[4], rss[4];
    int w = t >> 5, lane = t & 31;
    if (lane == 0) { rs[w] = s; rss[w] = ss; }
    __syncthreads();
    float S  = rs[0] + rs[1] + rs[2] + rs[3];
    float SS = rss[0] + rss[1] + rss[2] + rss[3];
    float mean = S * (1.f / DIM);
    float var  = SS * (1.f / DIM) - mean * mean;
    float rstd = rsqrtf(var + 1e-6f);
#pragma unroll
    for (int i = 0; i < 4; i++) {
        int c = t + i * 128;
        float o = (v[i] - mean) * rstd * gg[c] + bb[c];
        if (OH) ((__half*)out)[(size_t)row * DIM + c] = __float2half(o);
        else    ((float*)out)[(size_t)row * DIM + c]  = o;
    }
}

// ---------------- fp16 mma helpers ----------------
__device__ __forceinline__ unsigned s2u(const void* p) {
    return (unsigned)__cvta_generic_to_shared(p);
}

__device__ __forceinline__ void cp16(void* smem, const void* gmem) {
    asm volatile("cp.async.cg.shared.global [%0], [%1], 16;"
                 :: "r"(s2u(smem)), "l"(gmem));
}

__device__ __forceinline__ void mma_f16(float c[4], const unsigned a[4], const unsigned b[2]) {
    asm volatile(
        "mma.sync.aligned.m16n8k16.row.col.f32.f16.f16.f32 "
        "{%0,%1,%2,%3}, {%4,%5,%6,%7}, {%8,%9}, {%0,%1,%2,%3};"
        : "+f"(c[0]), "+f"(c[1]), "+f"(c[2]), "+f"(c[3])
        : "r"(a[0]), "r"(a[1]), "r"(a[2]), "r"(a[3]),
          "r"(b[0]), "r"(b[1]));
}

// ---------------- fp16 tensor-core GEMM (3-stage cp.async, BK=32) ---------
// BM=128, BN=128, 256 threads (8 warps, warp tile 64x32).
// EPI: 0 bias, 1 bias+residual(f32), 2 bias+relu
// SCAT: 0 plain, 4 fused-QKV (z selects W/bias/out; z==0 scales by 1/8)
// CH: output stored as half (1) or float (0)
constexpr int TG_BK   = 32;
constexpr int TG_LDA  = 40;
constexpr int TG_LDB  = 136;
constexpr int TG_STG  = 3;
constexpr int TG_SMEM = TG_STG * (128 * TG_LDA + TG_BK * TG_LDB) * 2;  // 56832 B

template<int EPI, int SCAT, int CH>
__global__ __launch_bounds__(256, 2)
void tgemm(const __half* __restrict__ A, const __half* __restrict__ W,
           const float* __restrict__ bias, const float* __restrict__ resid,
           void* __restrict__ Cv, int K, int lda, int ldb, int ldc,
           long long sA, long long sB, long long sC, QKVArgs qa) {
    constexpr int BK  = TG_BK;
    constexpr int LDA = TG_LDA;
    constexpr int LDB = TG_LDB;

    extern __shared__ char smbuf[];
    __half (*As)[128][LDA] = (__half(*)[128][LDA])smbuf;
    __half (*Bs)[BK][LDB]  = (__half(*)[BK][LDB])(smbuf + TG_STG * 128 * LDA * 2);

    const int tid  = threadIdx.x;
    const int w    = tid >> 5;
    const int lane = tid & 31;
    const int g    = lane >> 2;
    const int tq   = lane & 3;
    const int lane15 = lane & 15;
    const int aoff = (lane >> 4) << 3;
    const int wrow = (w & 1) * 64;
    const int wcol = (w >> 1) * 32;
    const int z    = blockIdx.z;
    const int row0 = blockIdx.y * 128;
    const int col0 = blockIdx.x * 128;

    const float* bias_p = bias;
    __half* Co_h = (__half*)Cv;
    float*  Co_f = (float*)Cv;
    if (SCAT == 4) {
        W      = qa.w[z];
        bias_p = qa.b[z];
        Co_h   = qa.o[z];
    } else {
        A += (size_t)z * sA;
        W += (size_t)z * sB;
    }

    const int arow = tid >> 1;
    const int acol = (tid & 1) * 16;
    const int brow = tid >> 4;
    const int bcol = (tid & 15) * 8;

    const __half* Ap = A + (size_t)(row0 + arow) * lda + acol;
    const __half* Wp = W + (size_t)brow * ldb + col0 + bcol;

    float C[4][4][4];
#pragma unroll
    for (int i = 0; i < 4; i++)
#pragma unroll
        for (int j = 0; j < 4; j++)
#pragma unroll
            for (int q = 0; q < 4; q++) C[i][j][q] = 0.f;

    const int nblk = K / BK;

    auto issue = [&](int buf, int blk) {
        const __half* ap = Ap + blk * BK;
        cp16(&As[buf][arow][acol],     ap);
        cp16(&As[buf][arow][acol + 8], ap + 8);
#pragma unroll
        for (int rr = 0; rr < 2; rr++)
            cp16(&Bs[buf][brow + rr * 16][bcol], Wp + (size_t)(blk * BK + rr * 16) * ldb);
        asm volatile("cp.async.commit_group;");
    };

    issue(0, 0);
    issue(1, 1);
    asm volatile("cp.async.wait_group 1;");
    __syncthreads();

    int s = 0;
    for (int blk = 0; blk < nblk; blk++) {
        if (blk + 2 < nblk) issue((blk + 2) % TG_STG, blk + 2);

#pragma unroll
        for (int ks = 0; ks < 2; ks++) {
            const int kb = ks * 16;
            unsigned af[4][4], bf[4][2];
#pragma unroll
            for (int mt = 0; mt < 4; mt++) {
                unsigned addr = s2u(&As[s][wrow + mt * 16 + lane15][kb + aoff]);
                asm volatile("ldmatrix.sync.aligned.m8n8.x4.shared.b16 {%0,%1,%2,%3}, [%4];"
                             : "=r"(af[mt][0]), "=r"(af[mt][1]), "=r"(af[mt][2]), "=r"(af[mt][3])
                             : "r"(addr));
            }
#pragma unroll
            for (int nt = 0; nt < 4; nt++) {
                unsigned addr = s2u(&Bs[s][kb + lane15][wcol + nt * 8]);
                asm volatile("ldmatrix.sync.aligned.m8n8.x2.trans.shared.b16 {%0,%1}, [%2];"
                             : "=r"(bf[nt][0]), "=r"(bf[nt][1])
                             : "r"(addr));
            }
#pragma unroll
            for (int mt = 0; mt < 4; mt++)
#pragma unroll
                for (int nt = 0; nt < 4; nt++)
                    mma_f16(C[mt][nt], af[mt], bf[nt]);
        }

        if (blk + 2 < nblk) {
            asm volatile("cp.async.wait_group 1;");
            __syncthreads();
        } else if (blk + 1 < nblk) {
            asm volatile("cp.async.wait_group 0;");
            __syncthreads();
        }
        s = (s + 1) % TG_STG;
    }

#pragma unroll
    for (int mt = 0; mt < 4; mt++) {
#pragma unroll
        for (int half = 0; half < 2; half++) {
            int r = row0 + wrow + mt * 16 + g + half * 8;
#pragma unroll
            for (int nt = 0; nt < 4; nt++) {
                int c = col0 + wcol + nt * 8 + tq * 2;
                float v0 = C[mt][nt][half * 2 + 0] + bias_p[c];
                float v1 = C[mt][nt][half * 2 + 1] + bias_p[c + 1];
                if (EPI == 1) {
                    const float* rp = resid + (size_t)r * ldc + c;
                    v0 += rp[0]; v1 += rp[1];
                }
                if (EPI == 2) { v0 = fmaxf(v0, 0.f); v1 = fmaxf(v1, 0.f); }
                if (SCAT == 4) {
                    if (z == 0) { v0 *= 0.125f; v1 *= 0.125f; }
                    int b = r >> 9, n = r & 511, hh = c >> 6, dd = c & 63;
                    *(__half2*)(Co_h + (((size_t)(b * NH + hh)) * SEQ + n) * HD + dd) =
                        __floats2half2_rn(v0, v1);
                } else {
                    if (CH)
                        *(__half2*)(Co_h + (size_t)z * sC + (size_t)r * ldc + c) =
                            __floats2half2_rn(v0, v1);
                    else
                        *(float2*)(Co_f + (size_t)z * sC + (size_t)r * ldc + c) =
                            make_float2(v0, v1);
                }
            }
        }
    }
}

// ---------------- fused flash attention (2 CTAs/SM) ----------------
constexpr int LDQ = 72;
constexpr int ATTN_SMEM = (128 * LDQ + 2 * 64 * LDQ + 2 * 64 * LDQ) * 2;  // 55296 B

__global__ __launch_bounds__(256, 2)
void attn_kernel(const int* __restrict__ lengths) {
    extern __shared__ __half sm[];
    __half (*Q_sm)[LDQ] = (__half(*)[LDQ])sm;
    __half (*K_sm)[LDQ] = (__half(*)[LDQ])(sm + 128 * LDQ);
    __half (*V_sm)[LDQ] = (__half(*)[LDQ])(sm + 256 * LDQ);

    const int tid  = threadIdx.x;
    const int w    = tid >> 5;
    const int lane = tid & 31;
    const int g    = lane >> 2;
    const int tq   = lane & 3;
    const int lane15 = lane & 15;
    const int aoff = (lane >> 4) << 3;
    const int bh = blockIdx.y;
    const int b  = bh >> 3;
    const int hh = bh & 7;
    const int q0 = blockIdx.x * 128;
    const int qbase = w * 16;
    const int len = lengths[b];

    const __half* Qg = g_q + ((size_t)bh * SEQ + q0) * HD;
    const __half* Kg = g_k + (size_t)bh * SEQ * HD;
    const __half* Vg = g_v + (size_t)bh * SEQ * HD;

    {
        int r = tid >> 1, cb = (tid & 1) * 32;
        const __half* qp = Qg + (size_t)r * HD + cb;
#pragma unroll
        for (int i = 0; i < 4; i++)
            *(uint4*)&Q_sm[r][cb + i * 8] = *(const uint4*)(qp + i * 8);
    }
    const int kr = tid >> 2, kc = (tid & 3) * 16;
    uint4 ka, kb2, va, vb;
    ka  = *(const uint4*)(Kg + (size_t)kr * HD + kc);
    kb2 = *(const uint4*)(Kg + (size_t)kr * HD + kc + 8);
    va  = *(const uint4*)(Vg + (size_t)kr * HD + kc);
    vb  = *(const uint4*)(Vg + (size_t)kr * HD + kc + 8);
    *(uint4*)&K_sm[kr][kc]     = ka;
    *(uint4*)&K_sm[kr][kc + 8] = kb2;
    *(uint4*)&V_sm[kr][kc]     = va;
    *(uint4*)&V_sm[kr][kc + 8] = vb;
    __syncthreads();

    unsigned qf[4][4];
#pragma unroll
    for (int k = 0; k < 4; k++) {
        unsigned addr = s2u(&Q_sm[qbase + lane15][k * 16 + aoff]);
        asm volatile("ldmatrix.sync.aligned.m8n8.x4.shared.b16 {%0,%1,%2,%3}, [%4];"
                     : "=r"(qf[k][0]), "=r"(qf[k][1]), "=r"(qf[k][2]), "=r"(qf[k][3])
                     : "r"(addr));
    }

    float ctx[8][4];
#pragma unroll
    for (int i = 0; i < 8; i++)
#pragma unroll
        for (int j = 0; j < 4; j++) ctx[i][j] = 0.f;
    float rs0 = 0.f, rs1 = 0.f;

    int s = 0;
    for (int c = 0; c < 8; c++) {
        if (c + 1 < 8) {
            const __half* kp = Kg + (size_t)((c + 1) * 64 + kr) * HD + kc;
            const __half* vp = Vg + (size_t)((c + 1) * 64 + kr) * HD + kc;
            ka  = *(const uint4*)(kp);
            kb2 = *(const uint4*)(kp + 8);
            va  = *(const uint4*)(vp);
            vb  = *(const uint4*)(vp + 8);
        }

        float S[8][4];
#pragma unroll
        for (int i = 0; i < 8; i++)
#pragma unroll
            for (int j = 0; j < 4; j++) S[i][j] = 0.f;
#pragma unroll
        for (int k = 0; k < 4; k++) {
            unsigned bk[4][4];
#pragma unroll
            for (int p = 0; p < 4; p++) {
                unsigned addr = s2u(&K_sm[s * 64 + p * 16 + lane15][k * 16 + aoff]);
                asm volatile("ldmatrix.sync.aligned.m8n8.x4.shared.b16 {%0,%1,%2,%3}, [%4];"
                             : "=r"(bk[p][0]), "=r"(bk[p][1]), "=r"(bk[p][2]), "=r"(bk[p][3])
                             : "r"(addr));
            }
#pragma unroll
            for (int p = 0; p < 4; p++) {
                unsigned bfa[2] = {bk[p][0], bk[p][2]};
                unsigned bfb[2] = {bk[p][1], bk[p][3]};
                mma_f16(S[2 * p],     qf[k], bfa);
                mma_f16(S[2 * p + 1], qf[k], bfb);
            }
        }

        unsigned pl[8], ph[8];
        const int kbase = c * 64 + tq * 2;
#pragma unroll
        for (int nt = 0; nt < 8; nt++) {
            int key = kbase + nt * 8;
            bool m0 = key < len, m1 = key + 1 < len;
            float e0 = m0 ? __expf(S[nt][0]) : 0.f;
            float e1 = m1 ? __expf(S[nt][1]) : 0.f;
            float e2 = m0 ? __expf(S[nt][2]) : 0.f;
            float e3 = m1 ? __expf(S[nt][3]) : 0.f;
            __half2 h0 = __floats2half2_rn(e0, e1);
            __half2 h1 = __floats2half2_rn(e2, e3);
            pl[nt] = *(unsigned*)&h0;
            ph[nt] = *(unsigned*)&h1;
            float2 f0 = __half22float2(h0);
            float2 f1 = __half22float2(h1);
            rs0 += f0.x + f0.y;
            rs1 += f1.x + f1.y;
        }

#pragma unroll
        for (int j = 0; j < 4; j++) {
            unsigned af[4] = {pl[2 * j], ph[2 * j], pl[2 * j + 1], ph[2 * j + 1]};
#pragma unroll
            for (int nt = 0; nt < 8; nt++) {
                unsigned bf[2];
                unsigned addr = s2u(&V_sm[s * 64 + j * 16 + lane15][nt * 8]);
                asm volatile("ldmatrix.sync.aligned.m8n8.x2.trans.shared.b16 {%0,%1}, [%2];"
                             : "=r"(bf[0]), "=r"(bf[1])
                             : "r"(addr));
                mma_f16(ctx[nt], af, bf);
            }
        }

        if (c + 1 < 8) {
            int ns = s ^ 1;
            *(uint4*)&K_sm[ns * 64 + kr][kc]     = ka;
            *(uint4*)&K_sm[ns * 64 + kr][kc + 8] = kb2;
            *(uint4*)&V_sm[ns * 64 + kr][kc]     = va;
            *(uint4*)&V_sm[ns * 64 + kr][kc + 8] = vb;
            __syncthreads();
            s = ns;
        }
    }

    rs0 += __shfl_xor_sync(0xffffffffu, rs0, 1);
    rs0 += __shfl_xor_sync(0xffffffffu, rs0, 2);
    rs1 += __shfl_xor_sync(0xffffffffu, rs1, 1);
    rs1 += __shfl_xor_sync(0xffffffffu, rs1, 2);
    float i0 = 1.f / rs0;
    float i1 = 1.f / rs1;

    int q = q0 + qbase + g;
#pragma unroll
    for (int nt = 0; nt < 8; nt++) {
        int col = hh * HD + nt * 8 + tq * 2;
        *(__half2*)(g_ctx + (size_t)(b * SEQ + q) * DIM + col) =
            __floats2half2_rn(ctx[nt][0] * i0, ctx[nt][1] * i0);
        *(__half2*)(g_ctx + (size_t)(b * SEQ + q + 8) * DIM + col) =
            __floats2half2_rn(ctx[nt][2] * i1, ctx[nt][3] * i1);
    }
}

// ---------------- outputs ----------------
__global__ void out1_kernel(float* __restrict__ out1) {
    int idx = blockIdx.x * blockDim.x + threadIdx.x;
    if (idx >= MR * DIM) return;
    int d = idx % DIM;
    int nb = idx / DIM;
    int b = nb % BATCH;
    int n = nb / BATCH;
    out1[idx] = g_hf[((size_t)b * SEQ + n) * DIM + d];
}

__global__ void infw_kernel(const float* __restrict__ W) {
    int mrow = blockIdx.x;
    int t = threadIdx.x;  // 64
    float a[NCLS] = {0, 0, 0}, bv2[NCLS] = {0, 0, 0};
    const float* xp = g_hf + (size_t)mrow * DIM;
    for (int d = t; d < DIM; d += 64) {
        float xv = xp[d];
#pragma unroll
        for (int c = 0; c < NCLS; c++) {
            a[c]   += xv * W[(size_t)d * NCLS + c];
            bv2[c] += xv * W[(size_t)(DIM + d) * NCLS + c];
        }
    }
    __shared__ float red[6][64];
#pragma unroll
    for (int c = 0; c < NCLS; c++) { red[c][t] = a[c]; red[3 + c][t] = bv2[c]; }
    __syncthreads();
    for (int sft = 32; sft >= 1; sft >>= 1) {
        if (t < sft) {
#pragma unroll
            for (int c = 0; c < 6; c++) red[c][t] += red[c][t + sft];
        }
        __syncthreads();
    }
    if (t == 0) {
#pragma unroll
        for (int c = 0; c < NCLS; c++) {
            g_la[mrow * NCLS + c] = red[c][0];
            g_lb[mrow * NCLS + c] = red[3 + c][0];
        }
    }
}

__global__ void pair_kernel(float* __restrict__ out2) {
    int idx = blockIdx.x * blockDim.x + threadIdx.x;
    if (idx >= SEQ * SEQ * BATCH) return;
    int b = idx % BATCH;
    int j = (idx / BATCH) % SEQ;
    int i = idx / (BATCH * SEQ);
    const float* lap = g_la + ((size_t)b * SEQ + i) * NCLS;
    const float* lbp = g_lb + ((size_t)b * SEQ + j) * NCLS;
    float v0 = lap[0] + lbp[0];
    float v1 = lap[1] + lbp[1];
    float v2 = lap[2] + lbp[2];
    float mx = fmaxf(v0, fmaxf(v1, v2));
    float lse = mx + logf(expf(v0 - mx) + expf(v1 - mx) + expf(v2 - mx));
    float* o = out2 + (size_t)idx * NCLS;
    o[0] = v0 - lse; o[1] = v1 - lse; o[2] = v2 - lse;
}

// ---------------- orchestration ----------------
extern "C" void kernel_launch(void* const* d_in, const int* in_sizes, int n_in,
                              void* d_out, int out_size) {
    (void)in_sizes; (void)n_in; (void)out_size;
    const int*   src     = (const int*)  d_in[0];
    const int*   lengths = (const int*)  d_in[1];
    const float* emb     = (const float*)d_in[2];
    const float* ln1_g   = (const float*)d_in[3];
    const float* ln1_b   = (const float*)d_in[4];
    const float* Wq      = (const float*)d_in[5];
    const float* bq      = (const float*)d_in[6];
    const float* Wk      = (const float*)d_in[7];
    const float* bk      = (const float*)d_in[8];
    const float* Wv      = (const float*)d_in[9];
    const float* bv      = (const float*)d_in[10];
    const float* Wo      = (const float*)d_in[11];
    const float* bo      = (const float*)d_in[12];
    const float* ln2_g   = (const float*)d_in[13];
    const float* ln2_b   = (const float*)d_in[14];
    const float* W1      = (const float*)d_in[15];
    const float* b1      = (const float*)d_in[16];
    const float* W2      = (const float*)d_in[17];
    const float* b2      = (const float*)d_in[18];
    const float* lnf_g   = (const float*)d_in[19];
    const float* lnf_b   = (const float*)d_in[20];
    const float* inf_W   = (const float*)d_in[21];
    float* out = (float*)d_out;

    float *px, *phf;
    __half *ph, *pq, *pk, *pv, *pctx, *pffn, *pwh;
    cudaGetSymbolAddress((void**)&px,   g_x);
    cudaGetSymbolAddress((void**)&phf,  g_hf);
    cudaGetSymbolAddress((void**)&ph,   g_h);
    cudaGetSymbolAddress((void**)&pq,   g_q);
    cudaGetSymbolAddress((void**)&pk,   g_k);
    cudaGetSymbolAddress((void**)&pv,   g_v);
    cudaGetSymbolAddress((void**)&pctx, g_ctx);
    cudaGetSymbolAddress((void**)&pffn, g_ffn);
    cudaGetSymbolAddress((void**)&pwh,  g_wh);

    cudaFuncSetAttribute(attn_kernel, cudaFuncAttributeMaxDynamicSharedMemorySize,
                         ATTN_SMEM);
    cudaFuncSetAttribute(tgemm<0, 4, 1>, cudaFuncAttributeMaxDynamicSharedMemorySize,
                         TG_SMEM);
    cudaFuncSetAttribute(tgemm<1, 0, 0>, cudaFuncAttributeMaxDynamicSharedMemorySize,
                         TG_SMEM);
    cudaFuncSetAttribute(tgemm<2, 0, 1>, cudaFuncAttributeMaxDynamicSharedMemorySize,
                         TG_SMEM);

    // one-time weight fp32->fp16 conversion
    const int nQ = NL * DIM * DIM;
    const int nF = NL * DIM * DFFN;
    f2h4_kernel<<<(nQ / 4 + 255) / 256, 256>>>(Wq, pwh + OWQ, nQ / 4);
    f2h4_kernel<<<(nQ / 4 + 255) / 256, 256>>>(Wk, pwh + OWK, nQ / 4);
    f2h4_kernel<<<(nQ / 4 + 255) / 256, 256>>>(Wv, pwh + OWV, nQ / 4);
    f2h4_kernel<<<(nQ / 4 + 255) / 256, 256>>>(Wo, pwh + OWO, nQ / 4);
    f2h4_kernel<<<(nF / 4 + 255) / 256, 256>>>(W1, pwh + OW1, nF / 4);
    f2h4_kernel<<<(nF / 4 + 255) / 256, 256>>>(W2, pwh + OW2, nF / 4);

    embed_kernel<<<(MR * DIM + 255) / 256, 256>>>(src, emb);

    QKVArgs qe = {};

    for (int l = 0; l < NL; l++) {
        const __half* wq = pwh + OWQ + (size_t)l * DIM * DIM;
        const __half* wk = pwh + OWK + (size_t)l * DIM * DIM;
        const __half* wv = pwh + OWV + (size_t)l * DIM * DIM;
        const __half* wo = pwh + OWO + (size_t)l * DIM * DIM;
        const __half* w1 = pwh + OW1 + (size_t)l * DIM * DFFN;
        const __half* w2 = pwh + OW2 + (size_t)l * DFFN * DIM;

        ln_kernel<1><<<MR, 128>>>(px, ph, ln1_g + l * DIM, ln1_b + l * DIM);

        QKVArgs qa;
        qa.w[0] = wq; qa.w[1] = wk; qa.w[2] = wv;
        qa.b[0] = bq + l * DIM; qa.b[1] = bk + l * DIM; qa.b[2] = bv + l * DIM;
        qa.o[0] = pq; qa.o[1] = pk; qa.o[2] = pv;
        dim3 gQKV(DIM / 128, MR / 128, 3);
        tgemm<0, 4, 1><<<gQKV, 256, TG_SMEM>>>(ph, nullptr, nullptr, nullptr, nullptr,
                                               DIM, DIM, DIM, DIM, 0, 0, 0, qa);

        dim3 gA(SEQ / 128, NBH);
        attn_kernel<<<gA, 256, ATTN_SMEM>>>(lengths);

        dim3 gD(DIM / 128, MR / 128, 1);
        tgemm<1, 0, 0><<<gD, 256, TG_SMEM>>>(pctx, wo, bo + l * DIM, px, px,
                                             DIM, DIM, DIM, DIM, 0, 0, 0, qe);

        ln_kernel<1><<<MR, 128>>>(px, ph, ln2_g + l * DIM, ln2_b + l * DIM);

        dim3 gF(DFFN / 128, MR / 128, 1);
        tgemm<2, 0, 1><<<gF, 256, TG_SMEM>>>(ph, w1, b1 + l * DFFN, nullptr, pffn,
                                             DIM, DIM, DFFN, DFFN, 0, 0, 0, qe);
        tgemm<1, 0, 0><<<gD, 256, TG_SMEM>>>(pffn, w2, b2 + l * DIM, px, px,
                                             DFFN, DFFN, DIM, DIM, 0, 0, 0, qe);
    }

    ln_kernel<0><<<MR, 128>>>(px, phf, lnf_g, lnf_b);

    out1_kernel<<<(MR * DIM + 255) / 256, 256>>>(out);
    infw_kernel<<<MR, 64>>>(inf_W);
    pair_kernel<<<(SEQ * SEQ * BATCH + 255) / 256, 256>>>(out + (size_t)MR * DIM);
}